// round 4
// baseline (speedup 1.0000x reference)
#include <cuda_runtime.h>
#include <math.h>

#define BB 64
#define CC 768
#define C2 1536
#define RR 96
#define EE 16

// ---- scratch (device globals) ----
__device__ float d_gT[CC * BB];        // pooled, [C][B]
__device__ float d_p1[6 * C2 * BB];    // gemm1 split-K partials
__device__ float d_h1T[C2 * BB];       // conv1+BN+GELU, [2C][B]
__device__ float d_pa[12 * RR * BB];   // ca1 split-K partials
__device__ float d_h2T[C2 * BB];       // gated, [2C][B]
__device__ float d_p2[12 * CC * BB];   // gemm2 split-K partials
__device__ float d_h3[BB * CC];        // conv2+BN+GELU, [B][C]
__device__ volatile unsigned long long g_bar;  // monotonic barrier ticket counter

__device__ __forceinline__ float gelu_exact(float z) {
    return 0.5f * z * (1.0f + erff(z * 0.7071067811865476f));
}
__device__ __forceinline__ float sig2(float z) {          // sigmoid(2z)
    return 1.0f / (1.0f + expf(-2.0f * z));
}

// grid-wide barrier: atomic arrive, NON-atomic volatile poll (no L2 atomic-ALU
// serialization from pollers). Monotonic counter -> safe across graph replays.
__device__ __forceinline__ void gbar(int nb) {
    __syncthreads();
    if (threadIdx.x == 0) {
        __threadfence();
        unsigned long long t = atomicAdd((unsigned long long*)&g_bar, 1ULL);
        unsigned long long tgt =
            (t / (unsigned long long)nb + 1ULL) * (unsigned long long)nb;
        while (g_bar < tgt) __nanosleep(128);
        __threadfence();  // acquire: order subsequent reads after flag read
    }
    __syncthreads();
}

// tiled partial GEMM: JT output channels (j0..j0+JT), k-range [k0, k0+kcnt),
// act K-major [K][64]; W row-major [N][ldw]. Thread tile: 4 b x NJ j.
// smem: s_act[KC][64], s_w[JT][KC+4]. JT = 16*NJ. kcnt % KC == 0.
// LOADACT=false: s_act is pre-filled by caller (kcnt must equal KC).
template<int JT, int NJ, int KC, bool LOADACT>
__device__ __forceinline__ void tile_mm(
    const float* __restrict__ W, int ldw,
    const float* __restrict__ actT,
    int j0, int k0, int kcnt,
    float4* acc, float* s_act, float* s_w) {
    const int tid = threadIdx.x;
    const int bg = tid & 15, jg = tid >> 4;
    for (int kk = 0; kk < kcnt; kk += KC) {
        if (LOADACT) {
            const float4* a4 = (const float4*)(actT + (k0 + kk) * BB);
            float4* sa4 = (float4*)s_act;
            for (int i = tid; i < KC * 16; i += 256) sa4[i] = a4[i];
        }
        // load w chunk [JT][KC], row pitch KC+4
        const float4* w4g = (const float4*)W;
        for (int f = tid; f < JT * (KC / 4); f += 256) {
            int j = f / (KC / 4), kq = f % (KC / 4);
            float4 v = w4g[((j0 + j) * ldw + k0 + kk) / 4 + kq];
            *(float4*)(s_w + j * (KC + 4) + kq * 4) = v;
        }
        __syncthreads();
        const float* aw = s_w + (jg * NJ) * (KC + 4);
#pragma unroll 4
        for (int k = 0; k < KC; k++) {
            float4 a = *(const float4*)(s_act + k * BB + bg * 4);
#pragma unroll
            for (int q = 0; q < NJ; q++) {
                float w = aw[q * (KC + 4) + k];
                acc[q].x = fmaf(a.x, w, acc[q].x);
                acc[q].y = fmaf(a.y, w, acc[q].y);
                acc[q].z = fmaf(a.z, w, acc[q].z);
                acc[q].w = fmaf(a.w, w, acc[q].w);
            }
        }
        __syncthreads();
    }
}

__global__ __launch_bounds__(256) void fused_kernel(
    const float4* __restrict__ x,
    const float* __restrict__ w1,   const float* __restrict__ b1,
    const float* __restrict__ bn1g, const float* __restrict__ bn1b,
    const float* __restrict__ bn1m, const float* __restrict__ bn1v,
    const float* __restrict__ caw1, const float* __restrict__ cab1,
    const float* __restrict__ caw2, const float* __restrict__ cab2,
    const float* __restrict__ w2,   const float* __restrict__ b2,
    const float* __restrict__ bn2g, const float* __restrict__ bn2b,
    const float* __restrict__ bn2m, const float* __restrict__ bn2v,
    const float* __restrict__ w3,   const float* __restrict__ b3,
    float* __restrict__ out, int nb) {
    __shared__ float s_act[96 * 64];   // 24 KB
    __shared__ float s_w[64 * 68];     // 17 KB
    __shared__ float s_sc[EE];
    const int tid = threadIdx.x;
    const int bg = tid & 15, jg = tid >> 4;

    // ---- stage 0: global average pool -> gT[C][B] ----
    {
        int warp = blockIdx.x * 8 + (tid >> 5);
        int lane = tid & 31;
        for (int r = warp; r < BB * CC; r += nb * 8) {
            const float4* p = x + (size_t)r * 256 + lane;
            float s = 0.f;
#pragma unroll
            for (int k = 0; k < 8; k++) {
                float4 v = p[32 * k];
                s += (v.x + v.y) + (v.z + v.w);
            }
#pragma unroll
            for (int o = 16; o; o >>= 1) s += __shfl_xor_sync(0xffffffffu, s, o);
            if (lane == 0) {
                int b = r / CC, c = r - b * CC;
                d_gT[c * BB + b] = s * (1.0f / 1024.0f);
            }
        }
    }
    gbar(nb);

    // ---- stage 1: gemm1 partials (24 j-tiles x 6 k-slices = 144 items) ----
    for (int it = blockIdx.x; it < 144; it += nb) {
        int jt = it % 24, ks = it / 24;
        float4 acc[4] = {};
        tile_mm<64, 4, 64, true>(w1, CC, d_gT, jt * 64, ks * 128, 128, acc, s_act, s_w);
#pragma unroll
        for (int q = 0; q < 4; q++) {
            int j = jt * 64 + jg * 4 + q;
            *(float4*)(d_p1 + (ks * C2 + j) * BB + bg * 4) = acc[q];
        }
    }
    gbar(nb);

    // ---- stage 2: reduce + BN + GELU -> h1T ----
    for (int idx = blockIdx.x * 256 + tid; idx < C2 * BB; idx += nb * 256) {
        float s = 0.f;
#pragma unroll
        for (int k = 0; k < 6; k++) s += d_p1[k * C2 * BB + idx];
        int j = idx >> 6;
        float y = s + b1[j];
        y = (y - bn1m[j]) * rsqrtf(bn1v[j] + 1e-5f) * bn1g[j] + bn1b[j];
        d_h1T[idx] = gelu_exact(y);
    }
    gbar(nb);

    // ---- stage 3: ca1 partials (3 j-tiles x 12 k-slices = 36 items) ----
    for (int it = blockIdx.x; it < 36; it += nb) {
        int jt = it % 3, ks = it / 3;
        float4 acc[2] = {};
        tile_mm<32, 2, 64, true>(caw1, C2, d_h1T, jt * 32, ks * 128, 128, acc, s_act, s_w);
#pragma unroll
        for (int q = 0; q < 2; q++) {
            int j = jt * 32 + jg * 2 + q;
            *(float4*)(d_pa + (ks * RR + j) * BB + bg * 4) = acc[q];
        }
    }
    gbar(nb);

    // ---- stage 4 (fused): reduce pa -> aT in smem, then ca2 + gating -> h2T ----
    {
        // every block builds the full aT[96][64] in s_act (reduce + bias + GELU)
        for (int i = tid; i < RR * BB; i += 256) {
            float s = 0.f;
#pragma unroll
            for (int ks = 0; ks < 12; ks++) s += d_pa[ks * (RR * BB) + i];
            s_act[i] = gelu_exact(s + cab1[i >> 6]);
        }
        __syncthreads();
        for (int it = blockIdx.x; it < 48; it += nb) {
            int j0 = it * 32;
            float4 acc[2] = {};
            tile_mm<32, 2, 96, false>(caw2, RR, (const float*)0, j0, 0, 96,
                                      acc, s_act, s_w);
#pragma unroll
            for (int q = 0; q < 2; q++) {
                int j = j0 + jg * 2 + q;
                float bias = cab2[j];
                float4 h = *(const float4*)(d_h1T + j * BB + bg * 4);
                float4 o;
                o.x = h.x * sig2(acc[q].x + bias);
                o.y = h.y * sig2(acc[q].y + bias);
                o.z = h.z * sig2(acc[q].z + bias);
                o.w = h.w * sig2(acc[q].w + bias);
                *(float4*)(d_h2T + j * BB + bg * 4) = o;
            }
        }
    }
    gbar(nb);

    // ---- stage 5: gemm2 partials (12 j-tiles x 12 k-slices = 144 items) ----
    for (int it = blockIdx.x; it < 144; it += nb) {
        int jt = it % 12, ks = it / 12;
        float4 acc[4] = {};
        tile_mm<64, 4, 64, true>(w2, C2, d_h2T, jt * 64, ks * 128, 128, acc, s_act, s_w);
#pragma unroll
        for (int q = 0; q < 4; q++) {
            int j = jt * 64 + jg * 4 + q;
            *(float4*)(d_p2 + (ks * CC + j) * BB + bg * 4) = acc[q];
        }
    }
    gbar(nb);

    // ---- stage 6: reduce + BN + GELU -> h3 [B][C] ----
    for (int idx = blockIdx.x * 256 + tid; idx < CC * BB; idx += nb * 256) {
        float s = 0.f;
#pragma unroll
        for (int k = 0; k < 12; k++) s += d_p2[k * CC * BB + idx];
        int j = idx >> 6, b = idx & 63;
        float y = s + b2[j];
        y = (y - bn2m[j]) * rsqrtf(bn2v[j] + 1e-5f) * bn2g[j] + bn2b[j];
        d_h3[b * CC + j] = gelu_exact(y);
    }
    gbar(nb);

    // ---- stage 7: scores + top-2 + softmax ----
    for (int b = blockIdx.x; b < BB; b += nb) {
        int w = tid >> 5, lane = tid & 31;
        const float* h = d_h3 + b * CC;
#pragma unroll
        for (int q = 0; q < 2; q++) {
            int e = w + 8 * q;
            const float* wr = w3 + e * CC;
            float s = 0.f;
#pragma unroll
            for (int i = 0; i < CC / 32; i++) {
                int k = lane + 32 * i;
                s = fmaf(h[k], wr[k], s);
            }
#pragma unroll
            for (int o = 16; o; o >>= 1) s += __shfl_xor_sync(0xffffffffu, s, o);
            if (lane == 0) s_sc[e] = s + b3[e];
        }
        __syncthreads();
        if (tid == 0) {
            int i0 = 0; float v0 = s_sc[0];
#pragma unroll
            for (int t = 1; t < EE; t++) { if (s_sc[t] > v0) { v0 = s_sc[t]; i0 = t; } }
            int i1 = -1; float v1 = -3.402823466e38f;
#pragma unroll
            for (int t = 0; t < EE; t++) {
                if (t != i0 && s_sc[t] > v1) { v1 = s_sc[t]; i1 = t; }
            }
            float e1  = expf((v1 - v0) * 0.5f);
            float inv = 1.0f / (1.0f + e1);
            out[b * 2 + 0]       = (float)i0;
            out[b * 2 + 1]       = (float)i1;
            out[128 + b * 2 + 0] = inv;
            out[128 + b * 2 + 1] = e1 * inv;
        }
        __syncthreads();
    }
}

extern "C" void kernel_launch(void* const* d_in, const int* in_sizes, int n_in,
                              void* d_out, int out_size) {
    const float* x     = (const float*)d_in[0];
    const float* w1    = (const float*)d_in[1];
    const float* b1    = (const float*)d_in[2];
    const float* bn1_g = (const float*)d_in[3];
    const float* bn1_b = (const float*)d_in[4];
    const float* bn1_m = (const float*)d_in[5];
    const float* bn1_v = (const float*)d_in[6];
    const float* caw1  = (const float*)d_in[7];
    const float* cab1  = (const float*)d_in[8];
    const float* caw2  = (const float*)d_in[9];
    const float* cab2  = (const float*)d_in[10];
    const float* w2    = (const float*)d_in[11];
    const float* b2    = (const float*)d_in[12];
    const float* bn2_g = (const float*)d_in[13];
    const float* bn2_b = (const float*)d_in[14];
    const float* bn2_m = (const float*)d_in[15];
    const float* bn2_v = (const float*)d_in[16];
    const float* w3    = (const float*)d_in[17];
    const float* b3    = (const float*)d_in[18];

    int nsm = 148;
    cudaDeviceGetAttribute(&nsm, cudaDevAttrMultiProcessorCount, 0);

    fused_kernel<<<nsm, 256>>>((const float4*)x,
        w1, b1, bn1_g, bn1_b, bn1_m, bn1_v,
        caw1, cab1, caw2, cab2,
        w2, b2, bn2_g, bn2_b, bn2_m, bn2_v,
        w3, b3, (float*)d_out, nsm);
}

// round 5
// speedup vs baseline: 1.2317x; 1.2317x over previous
#include <cuda_runtime.h>
#include <math.h>

#define BB 64
#define CC 768
#define C2 1536
#define RR 96
#define EE 16

// ---- scratch (device globals) ----
__device__ float d_gT[CC * BB];         // pooled, [C][B]
__device__ float d_p1[12 * C2 * BB];    // gemm1 split-K partials (12 slabs)
__device__ float d_h1T[C2 * BB];        // conv1+BN+GELU, [2C][B]
__device__ float d_pa[24 * RR * BB];    // ca1 split-K partials (24 slabs)
__device__ float d_aT[RR * BB];         // bottleneck, [R][B]
__device__ float d_h2T[C2 * BB];        // gated, [2C][B]
__device__ float d_p2[24 * CC * BB];    // gemm2 split-K partials (24 slabs)
__device__ float d_h3[BB * CC];         // conv2+BN+GELU, [B][C]
__device__ volatile unsigned long long g_bar;  // monotonic ticket counter

__device__ __forceinline__ float gelu_exact(float z) {
    return 0.5f * z * (1.0f + erff(z * 0.7071067811865476f));
}
__device__ __forceinline__ float sig2(float z) {          // sigmoid(2z)
    return 1.0f / (1.0f + expf(-2.0f * z));
}

// grid-wide barrier: atomic arrive, volatile-load poll, monotonic (replay-safe)
__device__ __forceinline__ void gbar(int nb) {
    __syncthreads();
    if (threadIdx.x == 0) {
        __threadfence();
        unsigned long long t = atomicAdd((unsigned long long*)&g_bar, 1ULL);
        unsigned long long tgt =
            (t / (unsigned long long)nb + 1ULL) * (unsigned long long)nb;
        while (g_bar < tgt) __nanosleep(128);
        __threadfence();  // acquire
    }
    __syncthreads();
}

__device__ __forceinline__ float4 unpack2(unsigned long long lo,
                                          unsigned long long hi) {
    float4 r;
    asm("mov.b64 {%0, %1}, %2;" : "=f"(r.x), "=f"(r.y) : "l"(lo));
    asm("mov.b64 {%0, %1}, %2;" : "=f"(r.z), "=f"(r.w) : "l"(hi));
    return r;
}

// tiled partial GEMM with packed f32x2 FMA.
// JT output channels (j0..j0+JT), k-range [k0,k0+kcnt), act K-major [K][64],
// W row-major [N][ldw]. Thread tile: 4 b x NJ j. acc: 2*NJ packed f32x2.
// smem: s_act[KC][64], s_w[JT][KC+4]. JT = 16*NJ. kcnt % KC == 0.
template<int JT, int NJ, int KC, bool LOADACT>
__device__ __forceinline__ void tile_mm(
    const float* __restrict__ W, int ldw,
    const float* __restrict__ actT,
    int j0, int k0, int kcnt,
    unsigned long long* acc, float* s_act, float* s_w) {
    const int tid = threadIdx.x;
    const int bg = tid & 15, jg = tid >> 4;
    for (int kk = 0; kk < kcnt; kk += KC) {
        if (LOADACT) {
            const float4* a4 = (const float4*)(actT + (k0 + kk) * BB);
            float4* sa4 = (float4*)s_act;
            for (int i = tid; i < KC * 16; i += 256) sa4[i] = a4[i];
        }
        const float4* w4g = (const float4*)W;
        for (int f = tid; f < JT * (KC / 4); f += 256) {
            int j = f / (KC / 4), kq = f % (KC / 4);
            float4 v = w4g[((j0 + j) * ldw + k0 + kk) / 4 + kq];
            *(float4*)(s_w + j * (KC + 4) + kq * 4) = v;
        }
        __syncthreads();
        const float* aw = s_w + (jg * NJ) * (KC + 4);
#pragma unroll 4
        for (int k = 0; k < KC; k++) {
            ulonglong2 av = *(const ulonglong2*)(s_act + k * BB + bg * 4);
#pragma unroll
            for (int q = 0; q < NJ; q++) {
                float w = aw[q * (KC + 4) + k];
                unsigned long long ww;
                asm("mov.b64 %0, {%1, %1};" : "=l"(ww) : "f"(w));
                asm("fma.rn.f32x2 %0, %1, %2, %0;"
                    : "+l"(acc[2 * q]) : "l"(av.x), "l"(ww));
                asm("fma.rn.f32x2 %0, %1, %2, %0;"
                    : "+l"(acc[2 * q + 1]) : "l"(av.y), "l"(ww));
            }
        }
        __syncthreads();
    }
}

__global__ __launch_bounds__(256) void fused_kernel(
    const float4* __restrict__ x,
    const float* __restrict__ w1,   const float* __restrict__ b1,
    const float* __restrict__ bn1g, const float* __restrict__ bn1b,
    const float* __restrict__ bn1m, const float* __restrict__ bn1v,
    const float* __restrict__ caw1, const float* __restrict__ cab1,
    const float* __restrict__ caw2, const float* __restrict__ cab2,
    const float* __restrict__ w2,   const float* __restrict__ b2,
    const float* __restrict__ bn2g, const float* __restrict__ bn2b,
    const float* __restrict__ bn2m, const float* __restrict__ bn2v,
    const float* __restrict__ w3,   const float* __restrict__ b3,
    float* __restrict__ out, int nb) {
    __shared__ float s_act[96 * 64];   // 24 KB
    __shared__ float s_w[64 * 68];     // 17 KB
    __shared__ float s_sc[EE];
    const int tid = threadIdx.x;
    const int bg = tid & 15, jg = tid >> 4;

    // ---- stage 0: global average pool -> gT[C][B] ----
    {
        int warp = blockIdx.x * 8 + (tid >> 5);
        int lane = tid & 31;
        for (int r = warp; r < BB * CC; r += nb * 8) {
            const float4* p = x + (size_t)r * 256 + lane;
            float s = 0.f;
#pragma unroll
            for (int k = 0; k < 8; k++) {
                float4 v = p[32 * k];
                s += (v.x + v.y) + (v.z + v.w);
            }
#pragma unroll
            for (int o = 16; o; o >>= 1) s += __shfl_xor_sync(0xffffffffu, s, o);
            if (lane == 0) {
                int b = r / CC, c = r - b * CC;
                d_gT[c * BB + b] = s * (1.0f / 1024.0f);
            }
        }
    }
    gbar(nb);

    // ---- stage 1: gemm1 partials (24 j-tiles x 12 k-slices = 288 items) ----
    for (int it = blockIdx.x; it < 288; it += nb) {
        int jt = it % 24, ks = it / 24;
        unsigned long long acc[8] = {};
        tile_mm<64, 4, 64, true>(w1, CC, d_gT, jt * 64, ks * 128, 128,
                                 acc, s_act, s_w);
#pragma unroll
        for (int q = 0; q < 4; q++) {
            int j = jt * 64 + jg * 4 + q;
            *(float4*)(d_p1 + (ks * C2 + j) * BB + bg * 4) =
                unpack2(acc[2 * q], acc[2 * q + 1]);
        }
    }
    gbar(nb);

    // ---- stage 2: reduce + BN + GELU -> h1T ----
    for (int idx = blockIdx.x * 256 + tid; idx < C2 * BB; idx += nb * 256) {
        float s = 0.f;
#pragma unroll
        for (int k = 0; k < 12; k++) s += d_p1[k * C2 * BB + idx];
        int j = idx >> 6;
        float y = s + b1[j];
        y = (y - bn1m[j]) * rsqrtf(bn1v[j] + 1e-5f) * bn1g[j] + bn1b[j];
        d_h1T[idx] = gelu_exact(y);
    }
    gbar(nb);

    // ---- stage 3: ca1 partials (3 j-tiles x 24 k-slices = 72 items) ----
    for (int it = blockIdx.x; it < 72; it += nb) {
        int jt = it % 3, ks = it / 3;
        unsigned long long acc[4] = {};
        tile_mm<32, 2, 64, true>(caw1, C2, d_h1T, jt * 32, ks * 64, 64,
                                 acc, s_act, s_w);
#pragma unroll
        for (int q = 0; q < 2; q++) {
            int j = jt * 32 + jg * 2 + q;
            *(float4*)(d_pa + (ks * RR + j) * BB + bg * 4) =
                unpack2(acc[2 * q], acc[2 * q + 1]);
        }
    }
    gbar(nb);

    // ---- stage 4: reduce + GELU -> aT ----
    for (int idx = blockIdx.x * 256 + tid; idx < RR * BB; idx += nb * 256) {
        float s = 0.f;
#pragma unroll
        for (int k = 0; k < 24; k++) s += d_pa[k * RR * BB + idx];
        int j = idx >> 6;
        d_aT[idx] = gelu_exact(s + cab1[j]);
    }
    gbar(nb);

    // ---- stage 5: ca2 (K=96) + sigmoid gating -> h2T (48 items) ----
    for (int it = blockIdx.x; it < 48; it += nb) {
        int j0 = it * 32;
        unsigned long long acc[4] = {};
        tile_mm<32, 2, 96, true>(caw2, RR, d_aT, j0, 0, 96, acc, s_act, s_w);
#pragma unroll
        for (int q = 0; q < 2; q++) {
            int j = j0 + jg * 2 + q;
            float bias = cab2[j];
            float4 z = unpack2(acc[2 * q], acc[2 * q + 1]);
            float4 h = *(const float4*)(d_h1T + j * BB + bg * 4);
            float4 o;
            o.x = h.x * sig2(z.x + bias);
            o.y = h.y * sig2(z.y + bias);
            o.z = h.z * sig2(z.z + bias);
            o.w = h.w * sig2(z.w + bias);
            *(float4*)(d_h2T + j * BB + bg * 4) = o;
        }
    }
    gbar(nb);

    // ---- stage 6: gemm2 partials (12 j-tiles x 24 k-slices = 288 items) ----
    for (int it = blockIdx.x; it < 288; it += nb) {
        int jt = it % 12, ks = it / 12;
        unsigned long long acc[8] = {};
        tile_mm<64, 4, 64, true>(w2, C2, d_h2T, jt * 64, ks * 64, 64,
                                 acc, s_act, s_w);
#pragma unroll
        for (int q = 0; q < 4; q++) {
            int j = jt * 64 + jg * 4 + q;
            *(float4*)(d_p2 + (ks * CC + j) * BB + bg * 4) =
                unpack2(acc[2 * q], acc[2 * q + 1]);
        }
    }
    gbar(nb);

    // ---- stage 7: reduce + BN + GELU -> h3 [B][C] ----
    for (int idx = blockIdx.x * 256 + tid; idx < CC * BB; idx += nb * 256) {
        float s = 0.f;
#pragma unroll
        for (int k = 0; k < 24; k++) s += d_p2[k * CC * BB + idx];
        int j = idx >> 6, b = idx & 63;
        float y = s + b2[j];
        y = (y - bn2m[j]) * rsqrtf(bn2v[j] + 1e-5f) * bn2g[j] + bn2b[j];
        d_h3[b * CC + j] = gelu_exact(y);
    }
    gbar(nb);

    // ---- stage 8: scores + top-2 + softmax ----
    for (int b = blockIdx.x; b < BB; b += nb) {
        int w = tid >> 5, lane = tid & 31;
        const float* h = d_h3 + b * CC;
#pragma unroll
        for (int q = 0; q < 2; q++) {
            int e = w + 8 * q;
            const float* wr = w3 + e * CC;
            float s = 0.f;
#pragma unroll
            for (int i = 0; i < CC / 32; i++) {
                int k = lane + 32 * i;
                s = fmaf(h[k], wr[k], s);
            }
#pragma unroll
            for (int o = 16; o; o >>= 1) s += __shfl_xor_sync(0xffffffffu, s, o);
            if (lane == 0) s_sc[e] = s + b3[e];
        }
        __syncthreads();
        if (tid == 0) {
            int i0 = 0; float v0 = s_sc[0];
#pragma unroll
            for (int t = 1; t < EE; t++) { if (s_sc[t] > v0) { v0 = s_sc[t]; i0 = t; } }
            int i1 = -1; float v1 = -3.402823466e38f;
#pragma unroll
            for (int t = 0; t < EE; t++) {
                if (t != i0 && s_sc[t] > v1) { v1 = s_sc[t]; i1 = t; }
            }
            float e1  = expf((v1 - v0) * 0.5f);
            float inv = 1.0f / (1.0f + e1);
            out[b * 2 + 0]       = (float)i0;
            out[b * 2 + 1]       = (float)i1;
            out[128 + b * 2 + 0] = inv;
            out[128 + b * 2 + 1] = e1 * inv;
        }
        __syncthreads();
    }
}

extern "C" void kernel_launch(void* const* d_in, const int* in_sizes, int n_in,
                              void* d_out, int out_size) {
    const float* x     = (const float*)d_in[0];
    const float* w1    = (const float*)d_in[1];
    const float* b1    = (const float*)d_in[2];
    const float* bn1_g = (const float*)d_in[3];
    const float* bn1_b = (const float*)d_in[4];
    const float* bn1_m = (const float*)d_in[5];
    const float* bn1_v = (const float*)d_in[6];
    const float* caw1  = (const float*)d_in[7];
    const float* cab1  = (const float*)d_in[8];
    const float* caw2  = (const float*)d_in[9];
    const float* cab2  = (const float*)d_in[10];
    const float* w2    = (const float*)d_in[11];
    const float* b2    = (const float*)d_in[12];
    const float* bn2_g = (const float*)d_in[13];
    const float* bn2_b = (const float*)d_in[14];
    const float* bn2_m = (const float*)d_in[15];
    const float* bn2_v = (const float*)d_in[16];
    const float* w3    = (const float*)d_in[17];
    const float* b3    = (const float*)d_in[18];

    int nsm = 148;
    cudaDeviceGetAttribute(&nsm, cudaDevAttrMultiProcessorCount, 0);
    int nb = 2 * nsm;  // 2 co-resident blocks per SM (84 KB smem / SM)

    fused_kernel<<<nb, 256>>>((const float4*)x,
        w1, b1, bn1_g, bn1_b, bn1_m, bn1_v,
        caw1, cab1, caw2, cab2,
        w2, b2, bn2_g, bn2_b, bn2_m, bn2_v,
        w3, b3, (float*)d_out, nb);
}